// round 17
// baseline (speedup 1.0000x reference)
#include <cuda_runtime.h>
#include <cuda_fp16.h>
#include <math.h>
#include <stdint.h>

#define B_TOK 16384
#define DIM   1024          // K
#define HID   2048
#define NE    4
#define NC    3
#define NTOT  (NE * HID)    // 8192 rows of folded W1 (N dimension)

#define BM 128
#define BN 64
#define BK 64               // 64 halfs = 128B per row
#define KITERS (DIM / BK)   // 16
#define STAGES 3
#define ASTG 16384          // A stage: 128*64*2
#define BSTG 8192           // B stage: 64*64*2
#define STG  (ASTG + BSTG)  // 24 KB / stage
#define SRED_OFF (STAGES * STG)              // 73728
#define DYN_SMEM (SRED_OFF + BM * NC * 4)    // 75264 (~73.5 KB)

// ---- device scratch (allocation-free) ----
__device__ __align__(1024) __half g_normed_h[(size_t)B_TOK * DIM];  // 32 MB
__device__ __align__(1024) __half g_w1h[(size_t)NTOT * DIM];        // 16 MB (K-major, g-folded)
__device__ __align__(1024) float  g_b1f[NTOT];                      // b1 + lnb@w1
__device__ __align__(1024) float  g_gate[B_TOK * NE];

// ============================ PTX helpers (sm_80-safe only) ============================
__device__ __forceinline__ uint32_t smem_u32(const void* p) {
    uint32_t a;
    asm("{ .reg .u64 t; cvta.to.shared.u64 t, %1; cvt.u32.u64 %0, t; }" : "=r"(a) : "l"(p));
    return a;
}
__device__ __forceinline__ void cp16(uint32_t sa, const void* g) {
    asm volatile("cp.async.cg.shared.global [%0], [%1], 16;" :: "r"(sa), "l"(g) : "memory");
}
#define CP_COMMIT() asm volatile("cp.async.commit_group;" ::: "memory")
#define CP_WAIT(n)  asm volatile("cp.async.wait_group %0;" :: "n"(n) : "memory")

#define LDSM4(r, a) \
    asm volatile("ldmatrix.sync.aligned.m8n8.x4.shared.b16 {%0,%1,%2,%3}, [%4];" \
        : "=r"((r)[0]), "=r"((r)[1]), "=r"((r)[2]), "=r"((r)[3]) : "r"(a))

// fp16-accumulate variant: D/C are 2 regs (4 halves). Rate test vs f32-acc.
#define MMA16816H(d, a, b) \
    asm volatile("mma.sync.aligned.m16n8k16.row.col.f16.f16.f16.f16 " \
        "{%0,%1}, {%2,%3,%4,%5}, {%6,%7}, {%0,%1};" \
        : "+r"((d)[0]), "+r"((d)[1]) \
        : "r"((a)[0]), "r"((a)[1]), "r"((a)[2]), "r"((a)[3]), "r"((b)[0]), "r"((b)[1]))

__device__ __forceinline__ float gelu_exact(float v) {
    return 0.5f * v * (1.0f + erff(v * 0.70710678118654752f));
}

// ============== K0: LayerNorm + gate softmax + out bias init (warp-per-row) ==============
__global__ __launch_bounds__(256) void ln_gate_kernel(
    const float* __restrict__ x,
    const float* __restrict__ gln_g, const float* __restrict__ gln_b,
    const float* __restrict__ gate_w, const float* __restrict__ gate_b,
    const float* __restrict__ ex_b2, float* __restrict__ out)
{
    const int warp = threadIdx.x >> 5, lane = threadIdx.x & 31;
    const int row = blockIdx.x * 8 + warp;

    const float4* xp = (const float4*)(x + (size_t)row * DIM);
    float4 xv[8];
#pragma unroll
    for (int j = 0; j < 8; j++) xv[j] = xp[lane + j * 32];

    float s = 0.f, ss = 0.f;
#pragma unroll
    for (int j = 0; j < 8; j++) {
        s  += xv[j].x + xv[j].y + xv[j].z + xv[j].w;
        ss += xv[j].x * xv[j].x + xv[j].y * xv[j].y
            + xv[j].z * xv[j].z + xv[j].w * xv[j].w;
    }
#pragma unroll
    for (int o = 16; o; o >>= 1) {
        s  += __shfl_xor_sync(0xffffffffu, s, o);
        ss += __shfl_xor_sync(0xffffffffu, ss, o);
    }
    const float mu = s * (1.0f / DIM);
    const float var = ss * (1.0f / DIM) - mu * mu;
    const float rstd = rsqrtf(var + 1e-5f);

    const float4* ggp = (const float4*)gln_g;
    const float4* gbp = (const float4*)gln_b;
    const float4* gwp = (const float4*)gate_w;
    __half2* np = (__half2*)(g_normed_h + (size_t)row * DIM);

    float l0 = 0.f, l1 = 0.f, l2 = 0.f, l3 = 0.f;
#pragma unroll
    for (int j = 0; j < 8; j++) {
        const int f = lane + j * 32;
        float4 nv;
        nv.x = (xv[j].x - mu) * rstd; nv.y = (xv[j].y - mu) * rstd;
        nv.z = (xv[j].z - mu) * rstd; nv.w = (xv[j].w - mu) * rstd;
        np[2 * f]     = __floats2half2_rn(nv.x, nv.y);
        np[2 * f + 1] = __floats2half2_rn(nv.z, nv.w);

        const float4 gg = ggp[f], gb = gbp[f];
        const float y0 = fmaf(nv.x, gg.x, gb.x);
        const float y1 = fmaf(nv.y, gg.y, gb.y);
        const float y2 = fmaf(nv.z, gg.z, gb.z);
        const float y3 = fmaf(nv.w, gg.w, gb.w);
        const int d0 = f * 4;
        float4 w;
        w = gwp[d0 + 0]; l0 += y0 * w.x; l1 += y0 * w.y; l2 += y0 * w.z; l3 += y0 * w.w;
        w = gwp[d0 + 1]; l0 += y1 * w.x; l1 += y1 * w.y; l2 += y1 * w.z; l3 += y1 * w.w;
        w = gwp[d0 + 2]; l0 += y2 * w.x; l1 += y2 * w.y; l2 += y2 * w.z; l3 += y2 * w.w;
        w = gwp[d0 + 3]; l0 += y3 * w.x; l1 += y3 * w.y; l2 += y3 * w.z; l3 += y3 * w.w;
    }
#pragma unroll
    for (int o = 16; o; o >>= 1) {
        l0 += __shfl_xor_sync(0xffffffffu, l0, o);
        l1 += __shfl_xor_sync(0xffffffffu, l1, o);
        l2 += __shfl_xor_sync(0xffffffffu, l2, o);
        l3 += __shfl_xor_sync(0xffffffffu, l3, o);
    }

    if (lane == 0) {
        float L[NE] = { l0 + gate_b[0], l1 + gate_b[1], l2 + gate_b[2], l3 + gate_b[3] };
        float m = L[0];
#pragma unroll
        for (int e = 1; e < NE; e++) m = fmaxf(m, L[e]);
        float sum = 0.f, ew[NE];
#pragma unroll
        for (int e = 0; e < NE; e++) { ew[e] = expf(L[e] - m); sum += ew[e]; }
        const float inv = 1.0f / sum;
#pragma unroll
        for (int e = 0; e < NE; e++) g_gate[row * NE + e] = ew[e] * inv;
#pragma unroll
        for (int c = 0; c < NC; c++) {
            float a = 0.f;
#pragma unroll
            for (int e = 0; e < NE; e++) a += ew[e] * inv * ex_b2[e * NC + c];
            out[row * NC + c] = a;
        }
    }
}

// ===== K1a: seed b1f = b1 =====
__global__ __launch_bounds__(256) void b1_init_kernel(const float* __restrict__ b1)
{
    const int i = blockIdx.x * 256 + threadIdx.x;
    g_b1f[i] = b1[i];
}

// ===== K1b: fold ln gain into w1 (K-major fp16) AND accumulate lnb@w1 into b1f =====
__global__ __launch_bounds__(256) void fold_w1_kernel(
    const float* __restrict__ w1, const float* __restrict__ lng,
    const float* __restrict__ lnb)
{
    __shared__ float tile[32][33];
    __shared__ float bpart[32];
    const int tx = threadIdx.x, ty = threadIdx.y;
    const int h0 = blockIdx.x * 32, d0 = blockIdx.y * 32, e = blockIdx.z;

    float bsum = 0.f;
#pragma unroll
    for (int i = 0; i < 4; i++) {
        const int d = d0 + ty + i * 8;
        const float raw = w1[((size_t)e * DIM + d) * HID + h0 + tx];
        tile[ty + i * 8][tx] = raw * __ldg(&lng[e * DIM + d]);
        bsum += raw * __ldg(&lnb[e * DIM + d]);
    }
    if (ty == 0) bpart[tx] = 0.f;
    __syncthreads();
    atomicAdd(&bpart[tx], bsum);
#pragma unroll
    for (int i = 0; i < 4; i++) {
        const int h = h0 + ty + i * 8;
        g_w1h[((size_t)e * HID + h) * DIM + d0 + tx] = __float2half_rn(tile[tx][ty + i * 8]);
    }
    __syncthreads();
    if (ty == 0) atomicAdd(&g_b1f[e * HID + h0 + tx], bpart[tx]);
}

// ============== K3: mma.sync fp16 GEMM with fp16 ACCUMULATE (rate probe) ==============
// fp16 acc chains only within one K=64 chunk (4 MMAs), promoted to fp32 each it:
// accumulation error ~4e-4 abs, quadrature with 3.1e-4 input quant -> ~5e-4 < 1e-3.
// If legacy HMMA f32-acc is half-rate (consumer-style), this doubles the MMA roof.
__global__ __launch_bounds__(256, 2) void gemm_kernel(
    const float* __restrict__ ex_w2, float* __restrict__ out)
{
    extern __shared__ __align__(1024) char smem[];
    float* sred = (float*)(smem + SRED_OFF);
    const uint32_t sb = smem_u32(smem);
    const int t = threadIdx.x;
    const int warp = t >> 5, lane = t & 31;
    const int row0 = blockIdx.x * BM;
    const int n0 = blockIdx.y * BN;
    const int wm = warp >> 1;
    const int wn = warp & 1;

    float acc[2][4][4];
#pragma unroll
    for (int mi = 0; mi < 2; mi++)
#pragma unroll
        for (int nf = 0; nf < 4; nf++)
#pragma unroll
            for (int q = 0; q < 4; q++) acc[mi][nf][q] = 0.f;

    const int lrow = t >> 3, lc = t & 7;
    const uint32_t ldst = lrow * 128 + ((lc ^ (lrow & 7)) * 16);
    const char* gA = (const char*)(g_normed_h + (size_t)(row0 + lrow) * DIM) + lc * 16;
    const char* gB = (const char*)(g_w1h + (size_t)(n0 + lrow) * DIM) + lc * 16;

    uint32_t aoff0[4], boff0[4];
    {
        const int arow = wm * 32 + (lane & 15);
        const int brow = wn * 32 + (lane & 15);
        const int hi = lane >> 4;
#pragma unroll
        for (int j = 0; j < 4; j++) {
            const int ks = (j + warp) & 3;
            const int c = ks * 2 + hi;
            aoff0[j] = arow * 128 + ((c ^ (arow & 7)) * 16);
            boff0[j] = ASTG + brow * 128 + ((c ^ (brow & 7)) * 16);
        }
    }

#pragma unroll
    for (int s = 0; s < STAGES - 1; s++) {
        const uint32_t sbase = sb + s * STG;
#pragma unroll
        for (int j = 0; j < 4; j++) cp16(sbase + ldst + j * 4096, gA + j * 65536);
#pragma unroll
        for (int j = 0; j < 2; j++) cp16(sbase + ASTG + ldst + j * 4096, gB + j * 65536);
        gA += 128; gB += 128;
        CP_COMMIT();
    }

    int stage = 0, wstage = STAGES - 1;
    for (int it = 0; it < KITERS; it++) {
        CP_WAIT(STAGES - 2);
        __syncthreads();
        if (it + STAGES - 1 < KITERS) {
            const uint32_t sbase = sb + wstage * STG;
#pragma unroll
            for (int j = 0; j < 4; j++) cp16(sbase + ldst + j * 4096, gA + j * 65536);
#pragma unroll
            for (int j = 0; j < 2; j++) cp16(sbase + ASTG + ldst + j * 4096, gB + j * 65536);
            gA += 128; gB += 128;
        }
        CP_COMMIT();
        wstage = (wstage + 1 == STAGES) ? 0 : wstage + 1;

        const uint32_t sS = sb + stage * STG;
        stage = (stage + 1 == STAGES) ? 0 : stage + 1;

        // fp16 accumulators for this K=64 chunk
        uint32_t acch[2][4][2];
#pragma unroll
        for (int mi = 0; mi < 2; mi++)
#pragma unroll
            for (int nf = 0; nf < 4; nf++) { acch[mi][nf][0] = 0u; acch[mi][nf][1] = 0u; }

#pragma unroll
        for (int ks = 0; ks < 4; ks++) {
            uint32_t a[2][4], bf[4][2];
            const uint32_t ab = sS + aoff0[ks];
            const uint32_t bb = sS + boff0[ks];
            LDSM4(a[0], ab);
            LDSM4(a[1], ab + 2048);
#pragma unroll
            for (int g = 0; g < 2; g++) {
                uint32_t r[4];
                LDSM4(r, bb + g * 2048);
                bf[2 * g][0] = r[0];     bf[2 * g][1] = r[2];
                bf[2 * g + 1][0] = r[1]; bf[2 * g + 1][1] = r[3];
            }
#pragma unroll
            for (int mi = 0; mi < 2; mi++)
#pragma unroll
                for (int nf = 0; nf < 4; nf++)
                    MMA16816H(acch[mi][nf], a[mi], bf[nf]);
        }

        // promote chunk sums to fp32
#pragma unroll
        for (int mi = 0; mi < 2; mi++)
#pragma unroll
            for (int nf = 0; nf < 4; nf++) {
                const float2 lo = __half22float2(*(const __half2*)&acch[mi][nf][0]);
                const float2 hi = __half22float2(*(const __half2*)&acch[mi][nf][1]);
                acc[mi][nf][0] += lo.x; acc[mi][nf][1] += lo.y;
                acc[mi][nf][2] += hi.x; acc[mi][nf][3] += hi.y;
            }
    }
    CP_WAIT(0);

    const int e = blockIdx.y >> 5;
    for (int i = t; i < BM * NC; i += 256) sred[i] = 0.f;
    __syncthreads();

#pragma unroll
    for (int mi = 0; mi < 2; mi++) {
        float s00 = 0.f, s01 = 0.f, s02 = 0.f;
        float s10 = 0.f, s11 = 0.f, s12 = 0.f;
#pragma unroll
        for (int nf = 0; nf < 4; nf++) {
            const int n = n0 + wn * 32 + nf * 8 + (lane & 3) * 2;
            const float b1a = __ldg(&g_b1f[n]), b1b = __ldg(&g_b1f[n + 1]);
            const float wa0 = __ldg(&ex_w2[n * 3 + 0]);
            const float wa1 = __ldg(&ex_w2[n * 3 + 1]);
            const float wa2 = __ldg(&ex_w2[n * 3 + 2]);
            const float wb0 = __ldg(&ex_w2[n * 3 + 3]);
            const float wb1 = __ldg(&ex_w2[n * 3 + 4]);
            const float wb2 = __ldg(&ex_w2[n * 3 + 5]);
            const float v00 = gelu_exact(acc[mi][nf][0] + b1a);
            const float v01 = gelu_exact(acc[mi][nf][1] + b1b);
            const float v10 = gelu_exact(acc[mi][nf][2] + b1a);
            const float v11 = gelu_exact(acc[mi][nf][3] + b1b);
            s00 += v00 * wa0 + v01 * wb0;
            s01 += v00 * wa1 + v01 * wb1;
            s02 += v00 * wa2 + v01 * wb2;
            s10 += v10 * wa0 + v11 * wb0;
            s11 += v10 * wa1 + v11 * wb1;
            s12 += v10 * wa2 + v11 * wb2;
        }
#pragma unroll
        for (int o = 2; o; o >>= 1) {
            s00 += __shfl_xor_sync(0xffffffffu, s00, o);
            s01 += __shfl_xor_sync(0xffffffffu, s01, o);
            s02 += __shfl_xor_sync(0xffffffffu, s02, o);
            s10 += __shfl_xor_sync(0xffffffffu, s10, o);
            s11 += __shfl_xor_sync(0xffffffffu, s11, o);
            s12 += __shfl_xor_sync(0xffffffffu, s12, o);
        }
        if ((lane & 3) == 0) {
            const int rl = wm * 32 + mi * 16 + (lane >> 2);
            atomicAdd(&sred[rl * NC + 0], s00);
            atomicAdd(&sred[rl * NC + 1], s01);
            atomicAdd(&sred[rl * NC + 2], s02);
            atomicAdd(&sred[(rl + 8) * NC + 0], s10);
            atomicAdd(&sred[(rl + 8) * NC + 1], s11);
            atomicAdd(&sred[(rl + 8) * NC + 2], s12);
        }
    }
    __syncthreads();

    if (t < BM) {
        const int row = row0 + t;
        const float gw = g_gate[row * NE + e];
        atomicAdd(&out[row * NC + 0], gw * sred[t * NC + 0]);
        atomicAdd(&out[row * NC + 1], gw * sred[t * NC + 1]);
        atomicAdd(&out[row * NC + 2], gw * sred[t * NC + 2]);
    }
}

// ==================================================================================
extern "C" void kernel_launch(void* const* d_in, const int* in_sizes, int n_in,
                              void* d_out, int out_size)
{
    const float* x       = (const float*)d_in[0];
    const float* gln_g   = (const float*)d_in[1];
    const float* gln_b   = (const float*)d_in[2];
    const float* gate_w  = (const float*)d_in[3];
    const float* gate_b  = (const float*)d_in[4];
    const float* ex_ln_g = (const float*)d_in[5];
    const float* ex_ln_b = (const float*)d_in[6];
    const float* ex_w1   = (const float*)d_in[7];
    const float* ex_b1   = (const float*)d_in[8];
    const float* ex_w2   = (const float*)d_in[9];
    const float* ex_b2   = (const float*)d_in[10];
    float* out = (float*)d_out;

    cudaFuncSetAttribute(gemm_kernel, cudaFuncAttributeMaxDynamicSharedMemorySize, DYN_SMEM);

    ln_gate_kernel<<<B_TOK / 8, 256>>>(x, gln_g, gln_b, gate_w, gate_b, ex_b2, out);
    b1_init_kernel<<<NTOT / 256, 256>>>(ex_b1);
    fold_w1_kernel<<<dim3(HID / 32, DIM / 32, NE), dim3(32, 8)>>>(ex_w1, ex_ln_g, ex_ln_b);
    gemm_kernel<<<dim3(B_TOK / BM, NTOT / BN), 256, DYN_SMEM>>>(ex_w2, out);
}